// round 14
// baseline (speedup 1.0000x reference)
#include <cuda_runtime.h>
#include <cuda_fp16.h>
#include <cstdint>

// ---------------------------------------------------------------------------
// GCN 2-layer forward on GB300 — round 14: GEMM1 on mma.m16n8k16.f16
// (fp16 mantissa == tf32 mantissa -> same accuracy, half the MMA+LDS work).
// gather1 reverted to the proven R12 4-wide loop.
//   h  = x @ W1                 (mma.sync f16, 50000x512 @ 512x256)
//   a1 = Dinv (A+I) Dinv h ; +b1 ; ELU ; dropout(p=0.25, jax threefry)
//   p  = a1 @ W2                (fused: group dot-product in gather1)
//   out= Dinv (A+I) Dinv p + b2
// ---------------------------------------------------------------------------

#define NMAX 50048
#define EMAX 1000000
#define CIN  512
#define CH   256
#define SCAN_NB ((NMAX + 255) / 256)   // 196 tiles

// GEMM1 tiling: CTA 128x256x32, fp16 operands
#define CTA_M 128
#define CTA_N 256
#define CTA_K 32
#define NSTG  (CIN / CTA_K)          // 16
#define APADB 80                     // A smem row pitch (bytes) = 32 halves + pad
#define BPADB 80                     // B smem row pitch (bytes)
#define SM_A_BYTES (CTA_M * APADB)               // 10240
#define SM_B_BYTES (CTA_N * BPADB)               // 20480
#define SM_STAGE   (SM_A_BYTES + SM_B_BYTES)     // 30720
#define SM_TOTAL   (2 * SM_STAGE)                // 61440

__device__ int    g_DEGI[NMAX];
__device__ float  g_DINV[NMAX];
__device__ int    g_ROWPTR[NMAX + 1];
__device__ int    g_CUR[NMAX];
__device__ int    g_PART[SCAN_NB];
__device__ int    g_SRC[EMAX];
__device__ float  g_NRM[EMAX];
__device__ float  g_H  [(size_t)NMAX * CH];
__device__ float  g_P  [NMAX];
__device__ __half g_W1HT[(size_t)CH * CIN];   // W1 transposed, fp16: [n][k]
__device__ int    g_is64;

__device__ __forceinline__ uint32_t smem_u32(const void* p) {
    uint32_t a;
    asm("{ .reg .u64 t; cvta.to.shared.u64 t, %1; cvt.u32.u64 %0, t; }"
        : "=r"(a) : "l"(p));
    return a;
}
__device__ __forceinline__ void cp_async16(uint32_t dst, const void* src) {
    asm volatile("cp.async.ca.shared.global [%0], [%1], 16;"
                 :: "r"(dst), "l"(src));
}
#define CP_COMMIT() asm volatile("cp.async.commit_group;" ::: "memory")
#define CP_WAIT(n)  asm volatile("cp.async.wait_group %0;" :: "n"(n) : "memory")

__device__ __forceinline__ void mma_f16(float* c,
                                        uint32_t a0, uint32_t a1,
                                        uint32_t a2, uint32_t a3,
                                        uint32_t b0, uint32_t b1) {
    asm volatile(
        "mma.sync.aligned.m16n8k16.row.col.f32.f16.f16.f32 "
        "{%0,%1,%2,%3}, {%4,%5,%6,%7}, {%8,%9}, {%0,%1,%2,%3};"
        : "+f"(c[0]), "+f"(c[1]), "+f"(c[2]), "+f"(c[3])
        : "r"(a0), "r"(a1), "r"(a2), "r"(a3), "r"(b0), "r"(b1));
}

// ---------------------------------------------------------------------------
__global__ void detect_kernel(const unsigned* __restrict__ words, int E) {
    if (threadIdx.x == 0 && blockIdx.x == 0) {
        int n = E < 256 ? E : 256;
        unsigned acc = 0u;
        for (int i = 0; i < n; i++) acc |= words[2 * i + 1];
        g_is64 = (acc == 0u) ? 1 : 0;
    }
}
__device__ __forceinline__ int edge_at(const void* ei, int is64, long long idx) {
    if (is64) return (int)((const long long*)ei)[idx];
    return ((const int*)ei)[idx];
}

// ---------------------------------------------------------------------------
__global__ void deg_zero_kernel(int M) {
    int v = blockIdx.x * blockDim.x + threadIdx.x;
    if (v < M) g_DEGI[v] = 0;
}
__global__ void deg_acc_kernel(const void* __restrict__ ei, int E) {
    int e = blockIdx.x * blockDim.x + threadIdx.x;
    if (e >= E) return;
    int d = edge_at(ei, g_is64, (long long)E + e);
    atomicAdd(&g_DEGI[d], 1);
}
__global__ void dinv_kernel(int M) {
    int v = blockIdx.x * blockDim.x + threadIdx.x;
    if (v < M) g_DINV[v] = rsqrtf((float)(g_DEGI[v] + 1));
}

// ---------------------------------------------------------------------------
// 3-phase parallel exclusive scan of DEGI -> ROWPTR, CUR
// ---------------------------------------------------------------------------
__device__ __forceinline__ int block_incl_scan(int val, int* smem32) {
    int lane = threadIdx.x & 31, wid = threadIdx.x >> 5;
    int v = val;
    #pragma unroll
    for (int o = 1; o < 32; o <<= 1) {
        int t = __shfl_up_sync(0xffffffffu, v, o);
        if (lane >= o) v += t;
    }
    if (lane == 31) smem32[wid] = v;
    __syncthreads();
    if (wid == 0) {
        int w = (lane < 8) ? smem32[lane] : 0;
        #pragma unroll
        for (int o = 1; o < 8; o <<= 1) {
            int t = __shfl_up_sync(0xffffffffu, w, o);
            if (lane >= o) w += t;
        }
        if (lane < 8) smem32[lane] = w;
    }
    __syncthreads();
    return v + (wid > 0 ? smem32[wid - 1] : 0);
}

__global__ __launch_bounds__(256) void scan1_kernel(int M) {
    __shared__ int sm32[32];
    int i = blockIdx.x * 256 + threadIdx.x;
    int d = (i < M) ? g_DEGI[i] : 0;
    int incl = block_incl_scan(d, sm32);
    if (threadIdx.x == 255) g_PART[blockIdx.x] = incl;
}

__global__ __launch_bounds__(256) void scan2_kernel(int nb) {
    __shared__ int sm32[32];
    int tid = threadIdx.x;
    int v = (tid < nb) ? g_PART[tid] : 0;
    int incl = block_incl_scan(v, sm32);
    if (tid < nb) g_PART[tid] = incl - v;   // exclusive
}

__global__ __launch_bounds__(256) void scan3_kernel(int M) {
    __shared__ int sm32[32];
    int i = blockIdx.x * 256 + threadIdx.x;
    int d = (i < M) ? g_DEGI[i] : 0;
    int incl = block_incl_scan(d, sm32);
    int off = g_PART[blockIdx.x] + incl - d;
    if (i < M) {
        g_ROWPTR[i] = off;
        g_CUR[i]    = off;
        if (i == M - 1) g_ROWPTR[M] = off + d;
    }
}

__global__ void fill_kernel(const void* __restrict__ ei, int E) {
    int e = blockIdx.x * blockDim.x + threadIdx.x;
    if (e >= E) return;
    int is64 = g_is64;
    int s = edge_at(ei, is64, e);
    int d = edge_at(ei, is64, (long long)E + e);
    int pos = atomicAdd(&g_CUR[d], 1);
    g_SRC[pos] = s;
    g_NRM[pos] = g_DINV[s] * g_DINV[d];
}

// ---------------------------------------------------------------------------
// W1 transpose + fp16 convert: g_W1HT[n*512+k] = half(W1[k*256+n])
// ---------------------------------------------------------------------------
__global__ void w1ht_kernel(const float* __restrict__ W1) {
    int idx = blockIdx.x * blockDim.x + threadIdx.x;
    if (idx >= CIN * CH) return;
    int k = idx / CH, n = idx % CH;
    g_W1HT[(size_t)n * CIN + k] = __float2half_rn(W1[idx]);
}

// ---------------------------------------------------------------------------
// GEMM1: g_H = X @ W1 via mma.sync.m16n8k16.f16.
// CTA 128x256, 8 warps (4m x 2n). A: LDG fp32 -> cvt fp16 -> STS (pipelined);
// B: cp.async from pre-converted g_W1HT ([n][k] so frag halves are contiguous).
// ---------------------------------------------------------------------------
__global__ __launch_bounds__(256, 1) void gemm1_mma_kernel(
    const float* __restrict__ X, int M)
{
    extern __shared__ char smc[];
    // align to 16B
    uint32_t raw = smem_u32(smc);
    uint32_t base = (raw + 15u) & ~15u;
    char* sm = smc + (base - raw);

    int tid  = threadIdx.x;
    int wid  = tid >> 5;
    int lane = tid & 31;
    int gid  = lane >> 2;      // 0..7
    int tig  = lane & 3;       // 0..3
    int wm   = wid >> 1;       // 0..3
    int wn   = wid & 1;        // 0..1

    int m0 = blockIdx.x * CTA_M;

    float acc[2][16][4];
    #pragma unroll
    for (int i = 0; i < 2; i++)
        #pragma unroll
        for (int j = 0; j < 16; j++)
            #pragma unroll
            for (int k = 0; k < 4; k++) acc[i][j][k] = 0.0f;

    // producer lambdas ------------------------------------------------------
    // B tile: 256 n-rows x 32 k-halves (64B) per stage, cp.async 16B x4/row
    auto issueB = [&](int s, int buf) {
        uint32_t baseB = base + buf * SM_STAGE + SM_A_BYTES;
        #pragma unroll
        for (int it = 0; it < 4; it++) {
            int id = it * 256 + tid;
            int n  = id >> 2, c = id & 3;
            cp_async16(baseB + (uint32_t)(n * BPADB + c * 16),
                       g_W1HT + (size_t)n * CIN + s * CTA_K + c * 8);
        }
    };
    // A tile: per thread 4 float4 loads -> 8 half2 regs
    uint32_t apre[8];
    auto loadA = [&](int s) {
        #pragma unroll
        for (int it = 0; it < 4; it++) {
            int id  = it * 256 + tid;
            int row = id >> 3, kq = id & 7;
            int gr  = m0 + row; if (gr > M - 1) gr = M - 1;
            float4 v = *(const float4*)(X + (size_t)gr * CIN + s * CTA_K + kq * 4);
            __half2 h0 = __floats2half2_rn(v.x, v.y);
            __half2 h1 = __floats2half2_rn(v.z, v.w);
            apre[it * 2 + 0] = *(uint32_t*)&h0;
            apre[it * 2 + 1] = *(uint32_t*)&h1;
        }
    };
    auto storeA = [&](int buf) {
        char* baseA = sm + buf * SM_STAGE;
        #pragma unroll
        for (int it = 0; it < 4; it++) {
            int id  = it * 256 + tid;
            int row = id >> 3, kq = id & 7;
            *(uint2*)(baseA + row * APADB + kq * 8) =
                make_uint2(apre[it * 2], apre[it * 2 + 1]);
        }
    };

    // prologue: stage 0
    issueB(0, 0);
    CP_COMMIT();
    loadA(0);
    storeA(0);

    for (int s = 0; s < NSTG; s++) {
        int buf = s & 1;
        CP_WAIT(0);
        __syncthreads();   // B(buf) arrived; A(buf) STS visible; prev compute closed

        if (s + 1 < NSTG) {
            issueB(s + 1, buf ^ 1);   // safe: buf^1 readers closed by the sync
            CP_COMMIT();
            loadA(s + 1);             // LDG latency hidden by compute below
        }

        const char* sA = sm + buf * SM_STAGE;
        const char* sB = sA + SM_A_BYTES;

        #pragma unroll
        for (int ks = 0; ks < 2; ks++) {             // 2 k16-slices per stage
            uint32_t a[2][4];
            #pragma unroll
            for (int mt = 0; mt < 2; mt++) {
                int r = wm * 32 + mt * 16 + gid;
                const char* p = sA + r * APADB + ks * 32 + tig * 4;
                a[mt][0] = *(const uint32_t*)(p);
                a[mt][1] = *(const uint32_t*)(p + 8 * APADB);
                a[mt][2] = *(const uint32_t*)(p + 16);
                a[mt][3] = *(const uint32_t*)(p + 8 * APADB + 16);
            }
            #pragma unroll
            for (int nt = 0; nt < 16; nt++) {
                int n = wn * 128 + nt * 8 + gid;
                const char* p = sB + n * BPADB + ks * 32 + tig * 4;
                uint32_t b0 = *(const uint32_t*)(p);
                uint32_t b1 = *(const uint32_t*)(p + 16);
                mma_f16(acc[0][nt], a[0][0], a[0][1], a[0][2], a[0][3], b0, b1);
                mma_f16(acc[1][nt], a[1][0], a[1][1], a[1][2], a[1][3], b0, b1);
            }
        }

        if (s + 1 < NSTG) storeA(buf ^ 1);  // buf^1 readers closed by this iter's sync
    }

    #pragma unroll
    for (int mt = 0; mt < 2; mt++) {
        int r0 = m0 + wm * 32 + mt * 16 + gid;
        #pragma unroll
        for (int nt = 0; nt < 16; nt++) {
            int c = wn * 128 + nt * 8 + 2 * tig;
            if (r0 < M)
                *(float2*)(g_H + (size_t)r0 * CH + c) =
                    make_float2(acc[mt][nt][0], acc[mt][nt][1]);
            if (r0 + 8 < M)
                *(float2*)(g_H + (size_t)(r0 + 8) * CH + c) =
                    make_float2(acc[mt][nt][2], acc[mt][nt][3]);
        }
    }
}

// ---------------------------------------------------------------------------
// threefry2x32, key = (0, 42), partitionable mode: bits = o0 ^ o1
// ---------------------------------------------------------------------------
__device__ __forceinline__ void threefry2x32(unsigned c0, unsigned c1,
                                             unsigned& o0, unsigned& o1) {
    const unsigned ks0 = 0u, ks1 = 42u;
    const unsigned ks2 = 0x1BD11BDAu ^ ks0 ^ ks1;
    unsigned x0 = c0 + ks0;
    unsigned x1 = c1 + ks1;
#define TF_ROUND(r) { x0 += x1; x1 = (x1 << (r)) | (x1 >> (32 - (r))); x1 ^= x0; }
    TF_ROUND(13) TF_ROUND(15) TF_ROUND(26) TF_ROUND(6)
    x0 += ks1; x1 += ks2 + 1u;
    TF_ROUND(17) TF_ROUND(29) TF_ROUND(16) TF_ROUND(24)
    x0 += ks2; x1 += ks0 + 2u;
    TF_ROUND(13) TF_ROUND(15) TF_ROUND(26) TF_ROUND(6)
    x0 += ks0; x1 += ks1 + 3u;
    TF_ROUND(17) TF_ROUND(29) TF_ROUND(16) TF_ROUND(24)
    x0 += ks1; x1 += ks2 + 4u;
    TF_ROUND(13) TF_ROUND(15) TF_ROUND(26) TF_ROUND(6)
    x0 += ks2; x1 += ks0 + 5u;
#undef TF_ROUND
    o0 = x0; o1 = x1;
}

__device__ __forceinline__ float dropout_elu(float acc, float bias, unsigned idx) {
    unsigned o0, o1;
    threefry2x32(0u, idx, o0, o1);
    unsigned bits = o0 ^ o1;
    float u = __uint_as_float((bits >> 9) | 0x3F800000u) - 1.0f;
    float val = acc + bias;
    val = val > 0.0f ? val : expm1f(val);
    return (u < 0.75f) ? val * (1.0f / 0.75f) : 0.0f;
}

// ---------------------------------------------------------------------------
// Layer-1 aggregate + epilogue + fused GEMM2 (proven R12 4-wide version).
// ---------------------------------------------------------------------------
__global__ __launch_bounds__(256) void gather1_kernel(
    const float* __restrict__ b1, const float* __restrict__ W2, int M)
{
    int grp = threadIdx.x >> 6;
    int t   = threadIdx.x & 63;
    int v   = blockIdx.x * 4 + grp;
    bool active = (v < M);
    int vv = active ? v : 0;

    const float4* __restrict__ H4 = (const float4*)g_H;

    float dv = g_DINV[vv];
    float4 h = H4[(size_t)vv * 64 + t];
    float s2 = dv * dv;
    float4 acc = make_float4(s2 * h.x, s2 * h.y, s2 * h.z, s2 * h.w);

    int beg = active ? g_ROWPTR[vv]     : 0;
    int end = active ? g_ROWPTR[vv + 1] : 0;

    int j = beg;
    for (; j + 4 <= end; j += 4) {
        int   s0 = g_SRC[j],      s1 = g_SRC[j + 1];
        int   s2i = g_SRC[j + 2], s3 = g_SRC[j + 3];
        float n0 = g_NRM[j],      n1 = g_NRM[j + 1];
        float n2 = g_NRM[j + 2],  n3 = g_NRM[j + 3];
        float4 r0 = H4[(size_t)s0 * 64 + t];
        float4 r1 = H4[(size_t)s1 * 64 + t];
        float4 r2 = H4[(size_t)s2i * 64 + t];
        float4 r3 = H4[(size_t)s3 * 64 + t];
        acc.x += n0 * r0.x + n1 * r1.x + n2 * r2.x + n3 * r3.x;
        acc.y += n0 * r0.y + n1 * r1.y + n2 * r2.y + n3 * r3.y;
        acc.z += n0 * r0.z + n1 * r1.z + n2 * r2.z + n3 * r3.z;
        acc.w += n0 * r0.w + n1 * r1.w + n2 * r2.w + n3 * r3.w;
    }
    for (; j < end; j++) {
        int   s0 = g_SRC[j];
        float n0 = g_NRM[j];
        float4 r0 = H4[(size_t)s0 * 64 + t];
        acc.x += n0 * r0.x;
        acc.y += n0 * r0.y;
        acc.z += n0 * r0.z;
        acc.w += n0 * r0.w;
    }

    float4 bb = ((const float4*)b1)[t];
    unsigned base = (unsigned)vv * CH + (unsigned)t * 4;
    float a0 = dropout_elu(acc.x, bb.x, base + 0);
    float a1 = dropout_elu(acc.y, bb.y, base + 1);
    float a2 = dropout_elu(acc.z, bb.z, base + 2);
    float a3 = dropout_elu(acc.w, bb.w, base + 3);

    float4 w = ((const float4*)W2)[t];
    float dot = a0 * w.x + a1 * w.y + a2 * w.z + a3 * w.w;
    #pragma unroll
    for (int o = 16; o > 0; o >>= 1)
        dot += __shfl_xor_sync(0xffffffffu, dot, o);

    __shared__ float red[8];
    int lane = t & 31, hw = t >> 5;
    if (lane == 0) red[grp * 2 + hw] = dot;
    __syncthreads();
    if (t == 0 && active) g_P[v] = red[grp * 2] + red[grp * 2 + 1];
}

// ---------------------------------------------------------------------------
// Layer-2 aggregate (CSR gather, scalar). One warp per node.
// ---------------------------------------------------------------------------
__global__ void gather2_kernel(const float* __restrict__ b2,
                               float* __restrict__ out, int M) {
    int gt   = blockIdx.x * blockDim.x + threadIdx.x;
    int warp = gt >> 5;
    int lane = gt & 31;
    if (warp >= M) return;
    int beg = g_ROWPTR[warp];
    int end = g_ROWPTR[warp + 1];
    float s = 0.0f;
    for (int e = beg + lane; e < end; e += 32)
        s += g_NRM[e] * g_P[g_SRC[e]];
    #pragma unroll
    for (int o = 16; o > 0; o >>= 1) s += __shfl_xor_sync(0xffffffffu, s, o);
    if (lane == 0) {
        float dv = g_DINV[warp];
        out[warp] = dv * dv * g_P[warp] + b2[0] + s;
    }
}

// ---------------------------------------------------------------------------
extern "C" void kernel_launch(void* const* d_in, const int* in_sizes, int n_in,
                              void* d_out, int out_size) {
    const float* x  = (const float*)d_in[0];
    const void*  ei = d_in[1];
    const float* W1 = (const float*)d_in[2];
    const float* b1 = (const float*)d_in[3];
    const float* W2 = (const float*)d_in[4];
    const float* b2 = (const float*)d_in[5];
    float* out = (float*)d_out;

    int M = in_sizes[0] / CIN;     // 50000
    int E = in_sizes[1] / 2;       // 800000
    int nb = (M + 255) / 256;      // 196

    static cudaStream_t s2 = nullptr;
    static cudaEvent_t evFork = nullptr, evJoin = nullptr;
    if (!s2) {
        cudaFuncSetAttribute(gemm1_mma_kernel,
                             cudaFuncAttributeMaxDynamicSharedMemorySize,
                             SM_TOTAL + 16);
        cudaStreamCreateWithFlags(&s2, cudaStreamNonBlocking);
        cudaEventCreateWithFlags(&evFork, cudaEventDisableTiming);
        cudaEventCreateWithFlags(&evJoin, cudaEventDisableTiming);
    }

    // ---- fork: CSR build on s2, GEMM1 on stream 0 ----
    cudaEventRecord(evFork, 0);
    cudaStreamWaitEvent(s2, evFork, 0);

    detect_kernel  <<<1, 32, 0, s2>>>((const unsigned*)ei, E);      // #1
    deg_zero_kernel<<<nb, 256, 0, s2>>>(M);                          // #2
    w1ht_kernel<<<(CIN * CH + 255) / 256, 256>>>(W1);                // #3 (s0)
    dim3 g1((M + CTA_M - 1) / CTA_M, 1);  // (391, 1)
    gemm1_mma_kernel<<<g1, 256, SM_TOTAL + 16>>>(x, M);              // #4 (s0)

    deg_acc_kernel <<<(E + 255) / 256, 256, 0, s2>>>(ei, E);         // #5
    dinv_kernel    <<<nb, 256, 0, s2>>>(M);                          // #6
    scan1_kernel   <<<nb, 256, 0, s2>>>(M);                          // #7
    scan2_kernel   <<<1, 256, 0, s2>>>(nb);                          // #8
    scan3_kernel   <<<nb, 256, 0, s2>>>(M);                          // #9
    fill_kernel    <<<(E + 255) / 256, 256, 0, s2>>>(ei, E);         // #10

    cudaEventRecord(evJoin, s2);
    cudaStreamWaitEvent(0, evJoin, 0);

    gather1_kernel<<<(M + 3) / 4, 256>>>(b1, W2, M);                 // #11
    gather2_kernel<<<(M * 32 + 255) / 256, 256>>>(b2, out, M);       // #12
}

// round 15
// speedup vs baseline: 1.4028x; 1.4028x over previous
#include <cuda_runtime.h>
#include <cstdint>

// ---------------------------------------------------------------------------
// GCN 2-layer forward on GB300 — round 15: back to R12 tf32 GEMM, but with
// 512 threads / 16 warps per CTA (2x latency-hiding; occ 12.5% -> 25%).
//   h  = x @ W1                 (mma.sync tf32, 50000x512 @ 512x256)
//   a1 = Dinv (A+I) Dinv h ; +b1 ; ELU ; dropout(p=0.25, jax threefry)
//   p  = a1 @ W2                (fused: group dot-product in gather1)
//   out= Dinv (A+I) Dinv p + b2
// ---------------------------------------------------------------------------

#define NMAX 50048
#define EMAX 1000000
#define CIN  512
#define CH   256
#define SCAN_NB ((NMAX + 255) / 256)   // 196 tiles

// GEMM1 tiling: CTA 128x256x32, 512 threads (16 warps, 4m x 4n)
#define CTA_M 128
#define CTA_N 256
#define CTA_K 32
#define NSTG  (CIN / CTA_K)          // 16
#define APAD  36
#define BPAD  264
#define SM_A_BYTES (CTA_M * APAD * 4)            // 18432
#define SM_B_BYTES (CTA_K * BPAD * 4)            // 33792
#define SM_STAGE   (SM_A_BYTES + SM_B_BYTES)     // 52224
#define SM_TOTAL   (2 * SM_STAGE)                // 104448

__device__ int    g_DEGI[NMAX];
__device__ float  g_DINV[NMAX];
__device__ int    g_ROWPTR[NMAX + 1];
__device__ int    g_CUR[NMAX];
__device__ int    g_PART[SCAN_NB];
__device__ int    g_SRC[EMAX];
__device__ float  g_NRM[EMAX];
__device__ float  g_H  [(size_t)NMAX * CH];
__device__ float  g_P  [NMAX];
__device__ float  g_W1R[(size_t)CIN * CH];
__device__ int    g_is64;

__device__ __forceinline__ float to_tf32(float x) {
    float r;
    asm("cvt.rna.tf32.f32 %0, %1;" : "=f"(r) : "f"(x));
    return r;
}
__device__ __forceinline__ uint32_t smem_u32(const void* p) {
    uint32_t a;
    asm("{ .reg .u64 t; cvta.to.shared.u64 t, %1; cvt.u32.u64 %0, t; }"
        : "=r"(a) : "l"(p));
    return a;
}
__device__ __forceinline__ void cp_async16(uint32_t dst, const void* src) {
    asm volatile("cp.async.ca.shared.global [%0], [%1], 16;"
                 :: "r"(dst), "l"(src));
}
#define CP_COMMIT() asm volatile("cp.async.commit_group;" ::: "memory")
#define CP_WAIT(n)  asm volatile("cp.async.wait_group %0;" :: "n"(n) : "memory")

__device__ __forceinline__ void mma_tf32(float* c, const float* a, const float* b) {
    asm volatile(
        "mma.sync.aligned.m16n8k8.row.col.f32.tf32.tf32.f32 "
        "{%0,%1,%2,%3}, {%4,%5,%6,%7}, {%8,%9}, {%0,%1,%2,%3};"
        : "+f"(c[0]), "+f"(c[1]), "+f"(c[2]), "+f"(c[3])
        : "r"(__float_as_uint(a[0])), "r"(__float_as_uint(a[1])),
          "r"(__float_as_uint(a[2])), "r"(__float_as_uint(a[3])),
          "r"(__float_as_uint(b[0])), "r"(__float_as_uint(b[1])));
}

// ---------------------------------------------------------------------------
__global__ void detect_kernel(const unsigned* __restrict__ words, int E) {
    if (threadIdx.x == 0 && blockIdx.x == 0) {
        int n = E < 256 ? E : 256;
        unsigned acc = 0u;
        for (int i = 0; i < n; i++) acc |= words[2 * i + 1];
        g_is64 = (acc == 0u) ? 1 : 0;
    }
}
__device__ __forceinline__ int edge_at(const void* ei, int is64, long long idx) {
    if (is64) return (int)((const long long*)ei)[idx];
    return ((const int*)ei)[idx];
}

// ---------------------------------------------------------------------------
__global__ void deg_zero_kernel(int M) {
    int v = blockIdx.x * blockDim.x + threadIdx.x;
    if (v < M) g_DEGI[v] = 0;
}
__global__ void deg_acc_kernel(const void* __restrict__ ei, int E) {
    int e = blockIdx.x * blockDim.x + threadIdx.x;
    if (e >= E) return;
    int d = edge_at(ei, g_is64, (long long)E + e);
    atomicAdd(&g_DEGI[d], 1);
}
__global__ void dinv_kernel(int M) {
    int v = blockIdx.x * blockDim.x + threadIdx.x;
    if (v < M) g_DINV[v] = rsqrtf((float)(g_DEGI[v] + 1));
}

// ---------------------------------------------------------------------------
// 3-phase parallel exclusive scan of DEGI -> ROWPTR, CUR
// ---------------------------------------------------------------------------
__device__ __forceinline__ int block_incl_scan(int val, int* smem32) {
    int lane = threadIdx.x & 31, wid = threadIdx.x >> 5;
    int v = val;
    #pragma unroll
    for (int o = 1; o < 32; o <<= 1) {
        int t = __shfl_up_sync(0xffffffffu, v, o);
        if (lane >= o) v += t;
    }
    if (lane == 31) smem32[wid] = v;
    __syncthreads();
    if (wid == 0) {
        int w = (lane < 8) ? smem32[lane] : 0;
        #pragma unroll
        for (int o = 1; o < 8; o <<= 1) {
            int t = __shfl_up_sync(0xffffffffu, w, o);
            if (lane >= o) w += t;
        }
        if (lane < 8) smem32[lane] = w;
    }
    __syncthreads();
    return v + (wid > 0 ? smem32[wid - 1] : 0);
}

__global__ __launch_bounds__(256) void scan1_kernel(int M) {
    __shared__ int sm32[32];
    int i = blockIdx.x * 256 + threadIdx.x;
    int d = (i < M) ? g_DEGI[i] : 0;
    int incl = block_incl_scan(d, sm32);
    if (threadIdx.x == 255) g_PART[blockIdx.x] = incl;
}

__global__ __launch_bounds__(256) void scan2_kernel(int nb) {
    __shared__ int sm32[32];
    int tid = threadIdx.x;
    int v = (tid < nb) ? g_PART[tid] : 0;
    int incl = block_incl_scan(v, sm32);
    if (tid < nb) g_PART[tid] = incl - v;   // exclusive
}

__global__ __launch_bounds__(256) void scan3_kernel(int M) {
    __shared__ int sm32[32];
    int i = blockIdx.x * 256 + threadIdx.x;
    int d = (i < M) ? g_DEGI[i] : 0;
    int incl = block_incl_scan(d, sm32);
    int off = g_PART[blockIdx.x] + incl - d;
    if (i < M) {
        g_ROWPTR[i] = off;
        g_CUR[i]    = off;
        if (i == M - 1) g_ROWPTR[M] = off + d;
    }
}

__global__ void fill_kernel(const void* __restrict__ ei, int E) {
    int e = blockIdx.x * blockDim.x + threadIdx.x;
    if (e >= E) return;
    int is64 = g_is64;
    int s = edge_at(ei, is64, e);
    int d = edge_at(ei, is64, (long long)E + e);
    int pos = atomicAdd(&g_CUR[d], 1);
    g_SRC[pos] = s;
    g_NRM[pos] = g_DINV[s] * g_DINV[d];
}

// ---------------------------------------------------------------------------
__global__ void w1r_kernel(const float* __restrict__ W1) {
    int idx = blockIdx.x * blockDim.x + threadIdx.x;
    if (idx < CIN * CH) g_W1R[idx] = to_tf32(W1[idx]);
}

// ---------------------------------------------------------------------------
// GEMM1: g_H = X @ W1 via mma.sync.m16n8k8 tf32.
// CTA 128x256, 16 warps (4m x 4n), warp tile 32x64. cp.async double buffer.
// ---------------------------------------------------------------------------
__global__ __launch_bounds__(512, 1) void gemm1_mma_kernel(
    const float* __restrict__ X, int M)
{
    extern __shared__ float sm[];
    uint32_t smb = smem_u32(sm);

    int tid  = threadIdx.x;
    int wid  = tid >> 5;
    int lane = tid & 31;
    int gid  = lane >> 2;      // 0..7
    int tig  = lane & 3;       // 0..3
    int wm   = wid >> 2;       // 0..3
    int wn   = wid & 3;        // 0..3

    int m0 = blockIdx.x * CTA_M;

    float acc[2][8][4];
    #pragma unroll
    for (int i = 0; i < 2; i++)
        #pragma unroll
        for (int j = 0; j < 8; j++)
            #pragma unroll
            for (int k = 0; k < 4; k++) acc[i][j][k] = 0.0f;

    auto issue = [&](int s, int buf) {
        uint32_t baseA = smb + buf * SM_STAGE;
        uint32_t baseB = baseA + SM_A_BYTES;
        // A tile: 128x32 floats = 1024 float4, 2 iters @512 threads
        #pragma unroll
        for (int it = 0; it < 2; it++) {
            int id  = it * 512 + tid;
            int ar = id >> 3, akq = id & 7;
            int grow = m0 + ar; if (grow > M - 1) grow = M - 1;
            cp_async16(baseA + (uint32_t)(ar * APAD + akq * 4) * 4,
                       X + (size_t)grow * CIN + s * CTA_K + akq * 4);
        }
        // B tile: 32x256 floats = 2048 float4, 4 iters @512 threads
        #pragma unroll
        for (int it = 0; it < 4; it++) {
            int id  = it * 512 + tid;
            int bk = id >> 6, bnc = id & 63;
            cp_async16(baseB + (uint32_t)(bk * BPAD + bnc * 4) * 4,
                       g_W1R + (size_t)(s * CTA_K + bk) * CH + bnc * 4);
        }
    };

    issue(0, 0);
    CP_COMMIT();

    for (int s = 0; s < NSTG; s++) {
        int buf = s & 1;
        if (s + 1 < NSTG) {
            issue(s + 1, buf ^ 1);
            CP_COMMIT();
            CP_WAIT(1);
        } else {
            CP_WAIT(0);
        }
        __syncthreads();

        const float* sA = sm + buf * (SM_STAGE / 4);
        const float* sB = sA + (SM_A_BYTES / 4);

        #pragma unroll
        for (int ks = 0; ks < 4; ks++) {
            float a[2][4];
            #pragma unroll
            for (int mt = 0; mt < 2; mt++) {
                int r = wm * 32 + mt * 16 + gid;
                int c = ks * 8 + tig;
                a[mt][0] = to_tf32(sA[r * APAD + c]);
                a[mt][1] = to_tf32(sA[(r + 8) * APAD + c]);
                a[mt][2] = to_tf32(sA[r * APAD + c + 4]);
                a[mt][3] = to_tf32(sA[(r + 8) * APAD + c + 4]);
            }
            float b[8][2];
            #pragma unroll
            for (int nt = 0; nt < 8; nt++) {
                int kk = ks * 8 + tig;
                int cc = wn * 64 + nt * 8 + gid;
                b[nt][0] = sB[kk * BPAD + cc];
                b[nt][1] = sB[(kk + 4) * BPAD + cc];
            }
            #pragma unroll
            for (int mt = 0; mt < 2; mt++)
                #pragma unroll
                for (int nt = 0; nt < 8; nt++)
                    mma_tf32(acc[mt][nt], a[mt], b[nt]);
        }
        __syncthreads();
    }

    #pragma unroll
    for (int mt = 0; mt < 2; mt++) {
        int r0 = m0 + wm * 32 + mt * 16 + gid;
        #pragma unroll
        for (int nt = 0; nt < 8; nt++) {
            int c = wn * 64 + nt * 8 + 2 * tig;
            if (r0 < M)
                *(float2*)(g_H + (size_t)r0 * CH + c) =
                    make_float2(acc[mt][nt][0], acc[mt][nt][1]);
            if (r0 + 8 < M)
                *(float2*)(g_H + (size_t)(r0 + 8) * CH + c) =
                    make_float2(acc[mt][nt][2], acc[mt][nt][3]);
        }
    }
}

// ---------------------------------------------------------------------------
// threefry2x32, key = (0, 42), partitionable mode: bits = o0 ^ o1
// ---------------------------------------------------------------------------
__device__ __forceinline__ void threefry2x32(unsigned c0, unsigned c1,
                                             unsigned& o0, unsigned& o1) {
    const unsigned ks0 = 0u, ks1 = 42u;
    const unsigned ks2 = 0x1BD11BDAu ^ ks0 ^ ks1;
    unsigned x0 = c0 + ks0;
    unsigned x1 = c1 + ks1;
#define TF_ROUND(r) { x0 += x1; x1 = (x1 << (r)) | (x1 >> (32 - (r))); x1 ^= x0; }
    TF_ROUND(13) TF_ROUND(15) TF_ROUND(26) TF_ROUND(6)
    x0 += ks1; x1 += ks2 + 1u;
    TF_ROUND(17) TF_ROUND(29) TF_ROUND(16) TF_ROUND(24)
    x0 += ks2; x1 += ks0 + 2u;
    TF_ROUND(13) TF_ROUND(15) TF_ROUND(26) TF_ROUND(6)
    x0 += ks0; x1 += ks1 + 3u;
    TF_ROUND(17) TF_ROUND(29) TF_ROUND(16) TF_ROUND(24)
    x0 += ks1; x1 += ks2 + 4u;
    TF_ROUND(13) TF_ROUND(15) TF_ROUND(26) TF_ROUND(6)
    x0 += ks2; x1 += ks0 + 5u;
#undef TF_ROUND
    o0 = x0; o1 = x1;
}

__device__ __forceinline__ float dropout_elu(float acc, float bias, unsigned idx) {
    unsigned o0, o1;
    threefry2x32(0u, idx, o0, o1);
    unsigned bits = o0 ^ o1;
    float u = __uint_as_float((bits >> 9) | 0x3F800000u) - 1.0f;
    float val = acc + bias;
    val = val > 0.0f ? val : expm1f(val);
    return (u < 0.75f) ? val * (1.0f / 0.75f) : 0.0f;
}

// ---------------------------------------------------------------------------
// Layer-1 aggregate + epilogue + fused GEMM2 (proven R12 4-wide version).
// ---------------------------------------------------------------------------
__global__ __launch_bounds__(256) void gather1_kernel(
    const float* __restrict__ b1, const float* __restrict__ W2, int M)
{
    int grp = threadIdx.x >> 6;
    int t   = threadIdx.x & 63;
    int v   = blockIdx.x * 4 + grp;
    bool active = (v < M);
    int vv = active ? v : 0;

    const float4* __restrict__ H4 = (const float4*)g_H;

    float dv = g_DINV[vv];
    float4 h = H4[(size_t)vv * 64 + t];
    float s2 = dv * dv;
    float4 acc = make_float4(s2 * h.x, s2 * h.y, s2 * h.z, s2 * h.w);

    int beg = active ? g_ROWPTR[vv]     : 0;
    int end = active ? g_ROWPTR[vv + 1] : 0;

    int j = beg;
    for (; j + 4 <= end; j += 4) {
        int   s0 = g_SRC[j],      s1 = g_SRC[j + 1];
        int   s2i = g_SRC[j + 2], s3 = g_SRC[j + 3];
        float n0 = g_NRM[j],      n1 = g_NRM[j + 1];
        float n2 = g_NRM[j + 2],  n3 = g_NRM[j + 3];
        float4 r0 = H4[(size_t)s0 * 64 + t];
        float4 r1 = H4[(size_t)s1 * 64 + t];
        float4 r2 = H4[(size_t)s2i * 64 + t];
        float4 r3 = H4[(size_t)s3 * 64 + t];
        acc.x += n0 * r0.x + n1 * r1.x + n2 * r2.x + n3 * r3.x;
        acc.y += n0 * r0.y + n1 * r1.y + n2 * r2.y + n3 * r3.y;
        acc.z += n0 * r0.z + n1 * r1.z + n2 * r2.z + n3 * r3.z;
        acc.w += n0 * r0.w + n1 * r1.w + n2 * r2.w + n3 * r3.w;
    }
    for (; j < end; j++) {
        int   s0 = g_SRC[j];
        float n0 = g_NRM[j];
        float4 r0 = H4[(size_t)s0 * 64 + t];
        acc.x += n0 * r0.x;
        acc.y += n0 * r0.y;
        acc.z += n0 * r0.z;
        acc.w += n0 * r0.w;
    }

    float4 bb = ((const float4*)b1)[t];
    unsigned base = (unsigned)vv * CH + (unsigned)t * 4;
    float a0 = dropout_elu(acc.x, bb.x, base + 0);
    float a1 = dropout_elu(acc.y, bb.y, base + 1);
    float a2 = dropout_elu(acc.z, bb.z, base + 2);
    float a3 = dropout_elu(acc.w, bb.w, base + 3);

    float4 w = ((const float4*)W2)[t];
    float dot = a0 * w.x + a1 * w.y + a2 * w.z + a3 * w.w;
    #pragma unroll
    for (int o = 16; o > 0; o >>= 1)
        dot += __shfl_xor_sync(0xffffffffu, dot, o);

    __shared__ float red[8];
    int lane = t & 31, hw = t >> 5;
    if (lane == 0) red[grp * 2 + hw] = dot;
    __syncthreads();
    if (t == 0 && active) g_P[v] = red[grp * 2] + red[grp * 2 + 1];
}

// ---------------------------------------------------------------------------
// Layer-2 aggregate (CSR gather, scalar). One warp per node.
// ---------------------------------------------------------------------------
__global__ void gather2_kernel(const float* __restrict__ b2,
                               float* __restrict__ out, int M) {
    int gt   = blockIdx.x * blockDim.x + threadIdx.x;
    int warp = gt >> 5;
    int lane = gt & 31;
    if (warp >= M) return;
    int beg = g_ROWPTR[warp];
    int end = g_ROWPTR[warp + 1];
    float s = 0.0f;
    for (int e = beg + lane; e < end; e += 32)
        s += g_NRM[e] * g_P[g_SRC[e]];
    #pragma unroll
    for (int o = 16; o > 0; o >>= 1) s += __shfl_xor_sync(0xffffffffu, s, o);
    if (lane == 0) {
        float dv = g_DINV[warp];
        out[warp] = dv * dv * g_P[warp] + b2[0] + s;
    }
}

// ---------------------------------------------------------------------------
extern "C" void kernel_launch(void* const* d_in, const int* in_sizes, int n_in,
                              void* d_out, int out_size) {
    const float* x  = (const float*)d_in[0];
    const void*  ei = d_in[1];
    const float* W1 = (const float*)d_in[2];
    const float* b1 = (const float*)d_in[3];
    const float* W2 = (const float*)d_in[4];
    const float* b2 = (const float*)d_in[5];
    float* out = (float*)d_out;

    int M = in_sizes[0] / CIN;     // 50000
    int E = in_sizes[1] / 2;       // 800000
    int nb = (M + 255) / 256;      // 196

    static cudaStream_t s2 = nullptr;
    static cudaEvent_t evFork = nullptr, evJoin = nullptr;
    if (!s2) {
        cudaFuncSetAttribute(gemm1_mma_kernel,
                             cudaFuncAttributeMaxDynamicSharedMemorySize, SM_TOTAL);
        cudaStreamCreateWithFlags(&s2, cudaStreamNonBlocking);
        cudaEventCreateWithFlags(&evFork, cudaEventDisableTiming);
        cudaEventCreateWithFlags(&evJoin, cudaEventDisableTiming);
    }

    // ---- fork: CSR build on s2, GEMM1 on stream 0 ----
    cudaEventRecord(evFork, 0);
    cudaStreamWaitEvent(s2, evFork, 0);

    detect_kernel  <<<1, 32, 0, s2>>>((const unsigned*)ei, E);      // #1
    deg_zero_kernel<<<nb, 256, 0, s2>>>(M);                          // #2
    w1r_kernel<<<(CIN * CH + 255) / 256, 256>>>(W1);                 // #3 (s0)
    dim3 g1((M + CTA_M - 1) / CTA_M, 1);  // (391, 1)
    gemm1_mma_kernel<<<g1, 512, SM_TOTAL>>>(x, M);                   // #4 (s0)

    deg_acc_kernel <<<(E + 255) / 256, 256, 0, s2>>>(ei, E);         // #5
    dinv_kernel    <<<nb, 256, 0, s2>>>(M);                          // #6
    scan1_kernel   <<<nb, 256, 0, s2>>>(M);                          // #7
    scan2_kernel   <<<1, 256, 0, s2>>>(nb);                          // #8
    scan3_kernel   <<<nb, 256, 0, s2>>>(M);                          // #9
    fill_kernel    <<<(E + 255) / 256, 256, 0, s2>>>(ei, E);         // #10

    cudaEventRecord(evJoin, s2);
    cudaStreamWaitEvent(0, evJoin, 0);

    gather1_kernel<<<(M + 3) / 4, 256>>>(b1, W2, M);                 // #11
    gather2_kernel<<<(M * 32 + 255) / 256, 256>>>(b2, out, M);       // #12
}

// round 16
// speedup vs baseline: 1.4592x; 1.0402x over previous
#include <cuda_runtime.h>
#include <cstdint>

// ---------------------------------------------------------------------------
// GCN 2-layer forward on GB300 — round 16: channel-split pipeline.
// gemm1 and gather1 are split into two 128-channel halves; gather1(half A)
// runs CONCURRENTLY with gemm1(half B) on a second stream.
//   h  = x @ W1                 (mma.sync tf32, 2 x 128-col launches)
//   a1 = Dinv (A+I) Dinv h ; +b1 ; ELU ; dropout(p=0.25, jax threefry)
//   p  = a1 @ W2                (fused: per-half partial dot, summed in gather2)
//   out= Dinv (A+I) Dinv p + b2
// ---------------------------------------------------------------------------

#define NMAX 50048
#define EMAX 1000000
#define CIN  512
#define CH   256
#define SCAN_NB ((NMAX + 255) / 256)   // 196 tiles

// GEMM1 tiling: CTA 128x128x32 (proven R5 shape), n0 selects column half
#define CTA_M 128
#define CTA_N 128
#define CTA_K 32
#define NSTG  (CIN / CTA_K)          // 16
#define APAD  36
#define BPAD  136
#define SM_A_BYTES (CTA_M * APAD * 4)            // 18432
#define SM_B_BYTES (CTA_K * BPAD * 4)            // 17408
#define SM_STAGE   (SM_A_BYTES + SM_B_BYTES)     // 35840
#define SM_TOTAL   (2 * SM_STAGE)                // 71680

__device__ int    g_DEGI[NMAX];
__device__ float  g_DINV[NMAX];
__device__ int    g_ROWPTR[NMAX + 1];
__device__ int    g_CUR[NMAX];
__device__ int    g_PART[SCAN_NB];
__device__ int    g_SRC[EMAX];
__device__ float  g_NRM[EMAX];
__device__ float  g_H  [(size_t)NMAX * CH];
__device__ float  g_Pa [NMAX];
__device__ float  g_Pb [NMAX];
__device__ float  g_W1R[(size_t)CIN * CH];
__device__ int    g_is64;

__device__ __forceinline__ float to_tf32(float x) {
    float r;
    asm("cvt.rna.tf32.f32 %0, %1;" : "=f"(r) : "f"(x));
    return r;
}
__device__ __forceinline__ uint32_t smem_u32(const void* p) {
    uint32_t a;
    asm("{ .reg .u64 t; cvta.to.shared.u64 t, %1; cvt.u32.u64 %0, t; }"
        : "=r"(a) : "l"(p));
    return a;
}
__device__ __forceinline__ void cp_async16(uint32_t dst, const void* src) {
    asm volatile("cp.async.ca.shared.global [%0], [%1], 16;"
                 :: "r"(dst), "l"(src));
}
#define CP_COMMIT() asm volatile("cp.async.commit_group;" ::: "memory")
#define CP_WAIT(n)  asm volatile("cp.async.wait_group %0;" :: "n"(n) : "memory")

__device__ __forceinline__ void mma_tf32(float* c, const float* a, const float* b) {
    asm volatile(
        "mma.sync.aligned.m16n8k8.row.col.f32.tf32.tf32.f32 "
        "{%0,%1,%2,%3}, {%4,%5,%6,%7}, {%8,%9}, {%0,%1,%2,%3};"
        : "+f"(c[0]), "+f"(c[1]), "+f"(c[2]), "+f"(c[3])
        : "r"(__float_as_uint(a[0])), "r"(__float_as_uint(a[1])),
          "r"(__float_as_uint(a[2])), "r"(__float_as_uint(a[3])),
          "r"(__float_as_uint(b[0])), "r"(__float_as_uint(b[1])));
}

// ---------------------------------------------------------------------------
__global__ void detect_kernel(const unsigned* __restrict__ words, int E) {
    if (threadIdx.x == 0 && blockIdx.x == 0) {
        int n = E < 256 ? E : 256;
        unsigned acc = 0u;
        for (int i = 0; i < n; i++) acc |= words[2 * i + 1];
        g_is64 = (acc == 0u) ? 1 : 0;
    }
}
__device__ __forceinline__ int edge_at(const void* ei, int is64, long long idx) {
    if (is64) return (int)((const long long*)ei)[idx];
    return ((const int*)ei)[idx];
}

// ---------------------------------------------------------------------------
__global__ void deg_zero_kernel(int M) {
    int v = blockIdx.x * blockDim.x + threadIdx.x;
    if (v < M) g_DEGI[v] = 0;
}
__global__ void deg_acc_kernel(const void* __restrict__ ei, int E) {
    int e = blockIdx.x * blockDim.x + threadIdx.x;
    if (e >= E) return;
    int d = edge_at(ei, g_is64, (long long)E + e);
    atomicAdd(&g_DEGI[d], 1);
}
__global__ void dinv_kernel(int M) {
    int v = blockIdx.x * blockDim.x + threadIdx.x;
    if (v < M) g_DINV[v] = rsqrtf((float)(g_DEGI[v] + 1));
}

// ---------------------------------------------------------------------------
// 3-phase parallel exclusive scan of DEGI -> ROWPTR, CUR
// ---------------------------------------------------------------------------
__device__ __forceinline__ int block_incl_scan(int val, int* smem32) {
    int lane = threadIdx.x & 31, wid = threadIdx.x >> 5;
    int v = val;
    #pragma unroll
    for (int o = 1; o < 32; o <<= 1) {
        int t = __shfl_up_sync(0xffffffffu, v, o);
        if (lane >= o) v += t;
    }
    if (lane == 31) smem32[wid] = v;
    __syncthreads();
    if (wid == 0) {
        int w = (lane < 8) ? smem32[lane] : 0;
        #pragma unroll
        for (int o = 1; o < 8; o <<= 1) {
            int t = __shfl_up_sync(0xffffffffu, w, o);
            if (lane >= o) w += t;
        }
        if (lane < 8) smem32[lane] = w;
    }
    __syncthreads();
    return v + (wid > 0 ? smem32[wid - 1] : 0);
}

__global__ __launch_bounds__(256) void scan1_kernel(int M) {
    __shared__ int sm32[32];
    int i = blockIdx.x * 256 + threadIdx.x;
    int d = (i < M) ? g_DEGI[i] : 0;
    int incl = block_incl_scan(d, sm32);
    if (threadIdx.x == 255) g_PART[blockIdx.x] = incl;
}

__global__ __launch_bounds__(256) void scan2_kernel(int nb) {
    __shared__ int sm32[32];
    int tid = threadIdx.x;
    int v = (tid < nb) ? g_PART[tid] : 0;
    int incl = block_incl_scan(v, sm32);
    if (tid < nb) g_PART[tid] = incl - v;   // exclusive
}

__global__ __launch_bounds__(256) void scan3_kernel(int M) {
    __shared__ int sm32[32];
    int i = blockIdx.x * 256 + threadIdx.x;
    int d = (i < M) ? g_DEGI[i] : 0;
    int incl = block_incl_scan(d, sm32);
    int off = g_PART[blockIdx.x] + incl - d;
    if (i < M) {
        g_ROWPTR[i] = off;
        g_CUR[i]    = off;
        if (i == M - 1) g_ROWPTR[M] = off + d;
    }
}

__global__ void fill_kernel(const void* __restrict__ ei, int E) {
    int e = blockIdx.x * blockDim.x + threadIdx.x;
    if (e >= E) return;
    int is64 = g_is64;
    int s = edge_at(ei, is64, e);
    int d = edge_at(ei, is64, (long long)E + e);
    int pos = atomicAdd(&g_CUR[d], 1);
    g_SRC[pos] = s;
    g_NRM[pos] = g_DINV[s] * g_DINV[d];
}

// ---------------------------------------------------------------------------
__global__ void w1r_kernel(const float* __restrict__ W1) {
    int idx = blockIdx.x * blockDim.x + threadIdx.x;
    if (idx < CIN * CH) g_W1R[idx] = to_tf32(W1[idx]);
}

// ---------------------------------------------------------------------------
// GEMM1 (half): g_H[:, n0:n0+128] = X @ W1[:, n0:n0+128].
// CTA 128x128, 8 warps (4m x 2n), warp tile 32x64. cp.async double buffer.
// ---------------------------------------------------------------------------
__global__ __launch_bounds__(256, 2) void gemm1_mma_kernel(
    const float* __restrict__ X, int M, int n0)
{
    extern __shared__ float sm[];
    uint32_t smb = smem_u32(sm);

    int tid  = threadIdx.x;
    int wid  = tid >> 5;
    int lane = tid & 31;
    int gid  = lane >> 2;
    int tig  = lane & 3;
    int wm   = wid >> 1;
    int wn   = wid & 1;

    int m0 = blockIdx.x * CTA_M;

    float acc[2][8][4];
    #pragma unroll
    for (int i = 0; i < 2; i++)
        #pragma unroll
        for (int j = 0; j < 8; j++)
            #pragma unroll
            for (int k = 0; k < 4; k++) acc[i][j][k] = 0.0f;

    auto issue = [&](int s, int buf) {
        uint32_t baseA = smb + buf * SM_STAGE;
        uint32_t baseB = baseA + SM_A_BYTES;
        #pragma unroll
        for (int it = 0; it < 4; it++) {
            int id  = it * 256 + tid;
            int ar = id >> 3, akq = id & 7;
            int grow = m0 + ar; if (grow > M - 1) grow = M - 1;
            cp_async16(baseA + (uint32_t)(ar * APAD + akq * 4) * 4,
                       X + (size_t)grow * CIN + s * CTA_K + akq * 4);
            int bk = id >> 5, bnc = id & 31;
            cp_async16(baseB + (uint32_t)(bk * BPAD + bnc * 4) * 4,
                       g_W1R + (size_t)(s * CTA_K + bk) * CH + n0 + bnc * 4);
        }
    };

    issue(0, 0);
    CP_COMMIT();

    for (int s = 0; s < NSTG; s++) {
        int buf = s & 1;
        if (s + 1 < NSTG) {
            issue(s + 1, buf ^ 1);
            CP_COMMIT();
            CP_WAIT(1);
        } else {
            CP_WAIT(0);
        }
        __syncthreads();

        const float* sA = sm + buf * (SM_STAGE / 4);
        const float* sB = sA + (SM_A_BYTES / 4);

        #pragma unroll
        for (int ks = 0; ks < 4; ks++) {
            float a[2][4];
            #pragma unroll
            for (int mt = 0; mt < 2; mt++) {
                int r = wm * 32 + mt * 16 + gid;
                int c = ks * 8 + tig;
                a[mt][0] = to_tf32(sA[r * APAD + c]);
                a[mt][1] = to_tf32(sA[(r + 8) * APAD + c]);
                a[mt][2] = to_tf32(sA[r * APAD + c + 4]);
                a[mt][3] = to_tf32(sA[(r + 8) * APAD + c + 4]);
            }
            float b[8][2];
            #pragma unroll
            for (int nt = 0; nt < 8; nt++) {
                int kk = ks * 8 + tig;
                int cc = wn * 64 + nt * 8 + gid;
                b[nt][0] = sB[kk * BPAD + cc];
                b[nt][1] = sB[(kk + 4) * BPAD + cc];
            }
            #pragma unroll
            for (int mt = 0; mt < 2; mt++)
                #pragma unroll
                for (int nt = 0; nt < 8; nt++)
                    mma_tf32(acc[mt][nt], a[mt], b[nt]);
        }
        __syncthreads();
    }

    #pragma unroll
    for (int mt = 0; mt < 2; mt++) {
        int r0 = m0 + wm * 32 + mt * 16 + gid;
        #pragma unroll
        for (int nt = 0; nt < 8; nt++) {
            int c = n0 + wn * 64 + nt * 8 + 2 * tig;
            if (r0 < M)
                *(float2*)(g_H + (size_t)r0 * CH + c) =
                    make_float2(acc[mt][nt][0], acc[mt][nt][1]);
            if (r0 + 8 < M)
                *(float2*)(g_H + (size_t)(r0 + 8) * CH + c) =
                    make_float2(acc[mt][nt][2], acc[mt][nt][3]);
        }
    }
}

// ---------------------------------------------------------------------------
// threefry2x32, key = (0, 42), partitionable mode: bits = o0 ^ o1
// ---------------------------------------------------------------------------
__device__ __forceinline__ void threefry2x32(unsigned c0, unsigned c1,
                                             unsigned& o0, unsigned& o1) {
    const unsigned ks0 = 0u, ks1 = 42u;
    const unsigned ks2 = 0x1BD11BDAu ^ ks0 ^ ks1;
    unsigned x0 = c0 + ks0;
    unsigned x1 = c1 + ks1;
#define TF_ROUND(r) { x0 += x1; x1 = (x1 << (r)) | (x1 >> (32 - (r))); x1 ^= x0; }
    TF_ROUND(13) TF_ROUND(15) TF_ROUND(26) TF_ROUND(6)
    x0 += ks1; x1 += ks2 + 1u;
    TF_ROUND(17) TF_ROUND(29) TF_ROUND(16) TF_ROUND(24)
    x0 += ks2; x1 += ks0 + 2u;
    TF_ROUND(13) TF_ROUND(15) TF_ROUND(26) TF_ROUND(6)
    x0 += ks0; x1 += ks1 + 3u;
    TF_ROUND(17) TF_ROUND(29) TF_ROUND(16) TF_ROUND(24)
    x0 += ks1; x1 += ks2 + 4u;
    TF_ROUND(13) TF_ROUND(15) TF_ROUND(26) TF_ROUND(6)
    x0 += ks2; x1 += ks0 + 5u;
#undef TF_ROUND
    o0 = x0; o1 = x1;
}

__device__ __forceinline__ float dropout_elu(float acc, float bias, unsigned idx) {
    unsigned o0, o1;
    threefry2x32(0u, idx, o0, o1);
    unsigned bits = o0 ^ o1;
    float u = __uint_as_float((bits >> 9) | 0x3F800000u) - 1.0f;
    float val = acc + bias;
    val = val > 0.0f ? val : expm1f(val);
    return (u < 0.75f) ? val * (1.0f / 0.75f) : 0.0f;
}

// ---------------------------------------------------------------------------
// Layer-1 aggregate (half) + epilogue + fused partial GEMM2.
// One warp per node, 32 threads x float4 = 128 channels [c0, c0+128).
// Same proven 4-wide edge loop. Partial W2 dot -> g_Pa (half=0) / g_Pb (1).
// ---------------------------------------------------------------------------
__global__ __launch_bounds__(256) void gather1_kernel(
    const float* __restrict__ b1, const float* __restrict__ W2,
    int M, int c0, int half)
{
    int wrp = threadIdx.x >> 5;              // 0..7
    int t   = threadIdx.x & 31;              // lane
    int v   = blockIdx.x * 8 + wrp;
    bool active = (v < M);
    int vv = active ? v : 0;

    const float4* __restrict__ H4 = (const float4*)g_H;
    int cq = (c0 >> 2) + t;                  // float4 index within row

    float dv = g_DINV[vv];
    float4 h = H4[(size_t)vv * 64 + cq];
    float s2 = dv * dv;
    float4 acc = make_float4(s2 * h.x, s2 * h.y, s2 * h.z, s2 * h.w);

    int beg = active ? g_ROWPTR[vv]     : 0;
    int end = active ? g_ROWPTR[vv + 1] : 0;

    int j = beg;
    for (; j + 4 <= end; j += 4) {
        int   s0 = g_SRC[j],      s1 = g_SRC[j + 1];
        int   s2i = g_SRC[j + 2], s3 = g_SRC[j + 3];
        float n0 = g_NRM[j],      n1 = g_NRM[j + 1];
        float n2 = g_NRM[j + 2],  n3 = g_NRM[j + 3];
        float4 r0 = H4[(size_t)s0 * 64 + cq];
        float4 r1 = H4[(size_t)s1 * 64 + cq];
        float4 r2 = H4[(size_t)s2i * 64 + cq];
        float4 r3 = H4[(size_t)s3 * 64 + cq];
        acc.x += n0 * r0.x + n1 * r1.x + n2 * r2.x + n3 * r3.x;
        acc.y += n0 * r0.y + n1 * r1.y + n2 * r2.y + n3 * r3.y;
        acc.z += n0 * r0.z + n1 * r1.z + n2 * r2.z + n3 * r3.z;
        acc.w += n0 * r0.w + n1 * r1.w + n2 * r2.w + n3 * r3.w;
    }
    for (; j < end; j++) {
        int   s0 = g_SRC[j];
        float n0 = g_NRM[j];
        float4 r0 = H4[(size_t)s0 * 64 + cq];
        acc.x += n0 * r0.x;
        acc.y += n0 * r0.y;
        acc.z += n0 * r0.z;
        acc.w += n0 * r0.w;
    }

    float4 bb = ((const float4*)b1)[cq];
    unsigned base = (unsigned)vv * CH + (unsigned)(c0 + t * 4);
    float a0 = dropout_elu(acc.x, bb.x, base + 0);
    float a1 = dropout_elu(acc.y, bb.y, base + 1);
    float a2 = dropout_elu(acc.z, bb.z, base + 2);
    float a3 = dropout_elu(acc.w, bb.w, base + 3);

    float4 w = ((const float4*)W2)[cq];
    float dot = a0 * w.x + a1 * w.y + a2 * w.z + a3 * w.w;
    #pragma unroll
    for (int o = 16; o > 0; o >>= 1)
        dot += __shfl_xor_sync(0xffffffffu, dot, o);

    if (t == 0 && active) {
        if (half == 0) g_Pa[v] = dot;
        else           g_Pb[v] = dot;
    }
}

// ---------------------------------------------------------------------------
// Layer-2 aggregate (CSR gather, scalar). One warp per node. P = Pa + Pb.
// ---------------------------------------------------------------------------
__global__ void gather2_kernel(const float* __restrict__ b2,
                               float* __restrict__ out, int M) {
    int gt   = blockIdx.x * blockDim.x + threadIdx.x;
    int warp = gt >> 5;
    int lane = gt & 31;
    if (warp >= M) return;
    int beg = g_ROWPTR[warp];
    int end = g_ROWPTR[warp + 1];
    float s = 0.0f;
    for (int e = beg + lane; e < end; e += 32) {
        int sidx = g_SRC[e];
        s += g_NRM[e] * (g_Pa[sidx] + g_Pb[sidx]);
    }
    #pragma unroll
    for (int o = 16; o > 0; o >>= 1) s += __shfl_xor_sync(0xffffffffu, s, o);
    if (lane == 0) {
        float dv = g_DINV[warp];
        out[warp] = dv * dv * (g_Pa[warp] + g_Pb[warp]) + b2[0] + s;
    }
}

// ---------------------------------------------------------------------------
extern "C" void kernel_launch(void* const* d_in, const int* in_sizes, int n_in,
                              void* d_out, int out_size) {
    const float* x  = (const float*)d_in[0];
    const void*  ei = d_in[1];
    const float* W1 = (const float*)d_in[2];
    const float* b1 = (const float*)d_in[3];
    const float* W2 = (const float*)d_in[4];
    const float* b2 = (const float*)d_in[5];
    float* out = (float*)d_out;

    int M = in_sizes[0] / CIN;     // 50000
    int E = in_sizes[1] / 2;       // 800000
    int nb = (M + 255) / 256;      // 196

    static cudaStream_t s2 = nullptr, s3 = nullptr;
    static cudaEvent_t evFork = nullptr, evCSR = nullptr,
                       evA = nullptr, evGa = nullptr;
    if (!s2) {
        cudaFuncSetAttribute(gemm1_mma_kernel,
                             cudaFuncAttributeMaxDynamicSharedMemorySize, SM_TOTAL);
        cudaStreamCreateWithFlags(&s2, cudaStreamNonBlocking);
        cudaStreamCreateWithFlags(&s3, cudaStreamNonBlocking);
        cudaEventCreateWithFlags(&evFork, cudaEventDisableTiming);
        cudaEventCreateWithFlags(&evCSR, cudaEventDisableTiming);
        cudaEventCreateWithFlags(&evA,   cudaEventDisableTiming);
        cudaEventCreateWithFlags(&evGa,  cudaEventDisableTiming);
    }

    dim3 g1((M + CTA_M - 1) / CTA_M, 1);   // 391 CTAs per half
    int gatherBlocks = (M + 7) / 8;        // 6250

    // ---- fork ----
    cudaEventRecord(evFork, 0);
    cudaStreamWaitEvent(s2, evFork, 0);

    // branch CSR (s2)
    detect_kernel  <<<1, 32, 0, s2>>>((const unsigned*)ei, E);      // #1
    deg_zero_kernel<<<nb, 256, 0, s2>>>(M);                          // #2
    // branch GEMM (s0)
    w1r_kernel<<<(CIN * CH + 255) / 256, 256>>>(W1);                 // #3
    gemm1_mma_kernel<<<g1, 256, SM_TOTAL>>>(x, M, 0);                // #4 half A
    cudaEventRecord(evA, 0);
    // rest of CSR (s2)
    deg_acc_kernel <<<(E + 255) / 256, 256, 0, s2>>>(ei, E);
    dinv_kernel    <<<nb, 256, 0, s2>>>(M);
    scan1_kernel   <<<nb, 256, 0, s2>>>(M);
    scan2_kernel   <<<1, 256, 0, s2>>>(nb);
    scan3_kernel   <<<nb, 256, 0, s2>>>(M);
    fill_kernel    <<<(E + 255) / 256, 256, 0, s2>>>(ei, E);
    cudaEventRecord(evCSR, s2);

    // gemm half B on s0 (runs after half A in stream order)
    gemm1_mma_kernel<<<g1, 256, SM_TOTAL>>>(x, M, 128);

    // gather half A on s3: needs gemm half A + CSR; concurrent with gemm half B
    cudaStreamWaitEvent(s3, evA, 0);
    cudaStreamWaitEvent(s3, evCSR, 0);
    gather1_kernel<<<gatherBlocks, 256, 0, s3>>>(b1, W2, M, 0, 0);
    cudaEventRecord(evGa, s3);

    // gather half B on s0 after gemm half B (stream order) + CSR
    cudaStreamWaitEvent(0, evCSR, 0);
    gather1_kernel<<<gatherBlocks, 256>>>(b1, W2, M, 128, 1);

    // join: gather2 needs both halves
    cudaStreamWaitEvent(0, evGa, 0);
    gather2_kernel<<<(M * 32 + 255) / 256, 256>>>(b2, out, M);
}

// round 17
// speedup vs baseline: 1.5492x; 1.0617x over previous
#include <cuda_runtime.h>
#include <cuda_fp16.h>
#include <cstdint>

// ---------------------------------------------------------------------------
// GCN 2-layer forward on GB300 — round 17: fp16 H + one-warp-per-row gather.
// A full 256-ch row is ONE warp LDG.128 (512B) -> half the warp-LDG count
// and half the bytes of every previous gather variant.
//   h  = x @ W1                 (mma.sync tf32 128x256, fp16 output)
//   a1 = Dinv (A+I) Dinv h ; +b1 ; ELU ; dropout(p=0.25, jax threefry)
//   p  = a1 @ W2                (fused: warp dot-product in gather1)
//   out= Dinv (A+I) Dinv p + b2
// ---------------------------------------------------------------------------

#define NMAX 50048
#define EMAX 1000000
#define CIN  512
#define CH   256
#define SCAN_NB ((NMAX + 255) / 256)   // 196 tiles

// GEMM1 tiling: CTA 128x256x32 (proven R12 shape)
#define CTA_M 128
#define CTA_N 256
#define CTA_K 32
#define NSTG  (CIN / CTA_K)          // 16
#define APAD  36
#define BPAD  264
#define SM_A_BYTES (CTA_M * APAD * 4)            // 18432
#define SM_B_BYTES (CTA_K * BPAD * 4)            // 33792
#define SM_STAGE   (SM_A_BYTES + SM_B_BYTES)     // 52224
#define SM_TOTAL   (2 * SM_STAGE)                // 104448

__device__ int    g_DEGI[NMAX];
__device__ float  g_DINV[NMAX];
__device__ int    g_ROWPTR[NMAX + 1];
__device__ int    g_CUR[NMAX];
__device__ int    g_PART[SCAN_NB];
__device__ int    g_SRC[EMAX];
__device__ float  g_NRM[EMAX];
__device__ __half g_H [(size_t)NMAX * CH];
__device__ float  g_P  [NMAX];
__device__ float  g_W1R[(size_t)CIN * CH];
__device__ int    g_is64;

__device__ __forceinline__ float to_tf32(float x) {
    float r;
    asm("cvt.rna.tf32.f32 %0, %1;" : "=f"(r) : "f"(x));
    return r;
}
__device__ __forceinline__ uint32_t smem_u32(const void* p) {
    uint32_t a;
    asm("{ .reg .u64 t; cvta.to.shared.u64 t, %1; cvt.u32.u64 %0, t; }"
        : "=r"(a) : "l"(p));
    return a;
}
__device__ __forceinline__ void cp_async16(uint32_t dst, const void* src) {
    asm volatile("cp.async.ca.shared.global [%0], [%1], 16;"
                 :: "r"(dst), "l"(src));
}
#define CP_COMMIT() asm volatile("cp.async.commit_group;" ::: "memory")
#define CP_WAIT(n)  asm volatile("cp.async.wait_group %0;" :: "n"(n) : "memory")

__device__ __forceinline__ void mma_tf32(float* c, const float* a, const float* b) {
    asm volatile(
        "mma.sync.aligned.m16n8k8.row.col.f32.tf32.tf32.f32 "
        "{%0,%1,%2,%3}, {%4,%5,%6,%7}, {%8,%9}, {%0,%1,%2,%3};"
        : "+f"(c[0]), "+f"(c[1]), "+f"(c[2]), "+f"(c[3])
        : "r"(__float_as_uint(a[0])), "r"(__float_as_uint(a[1])),
          "r"(__float_as_uint(a[2])), "r"(__float_as_uint(a[3])),
          "r"(__float_as_uint(b[0])), "r"(__float_as_uint(b[1])));
}

// ---------------------------------------------------------------------------
__global__ void detect_kernel(const unsigned* __restrict__ words, int E) {
    if (threadIdx.x == 0 && blockIdx.x == 0) {
        int n = E < 256 ? E : 256;
        unsigned acc = 0u;
        for (int i = 0; i < n; i++) acc |= words[2 * i + 1];
        g_is64 = (acc == 0u) ? 1 : 0;
    }
}
__device__ __forceinline__ int edge_at(const void* ei, int is64, long long idx) {
    if (is64) return (int)((const long long*)ei)[idx];
    return ((const int*)ei)[idx];
}

// ---------------------------------------------------------------------------
__global__ void deg_zero_kernel(int M) {
    int v = blockIdx.x * blockDim.x + threadIdx.x;
    if (v < M) g_DEGI[v] = 0;
}
__global__ void deg_acc_kernel(const void* __restrict__ ei, int E) {
    int e = blockIdx.x * blockDim.x + threadIdx.x;
    if (e >= E) return;
    int d = edge_at(ei, g_is64, (long long)E + e);
    atomicAdd(&g_DEGI[d], 1);
}
__global__ void dinv_kernel(int M) {
    int v = blockIdx.x * blockDim.x + threadIdx.x;
    if (v < M) g_DINV[v] = rsqrtf((float)(g_DEGI[v] + 1));
}

// ---------------------------------------------------------------------------
// 3-phase parallel exclusive scan of DEGI -> ROWPTR, CUR
// ---------------------------------------------------------------------------
__device__ __forceinline__ int block_incl_scan(int val, int* smem32) {
    int lane = threadIdx.x & 31, wid = threadIdx.x >> 5;
    int v = val;
    #pragma unroll
    for (int o = 1; o < 32; o <<= 1) {
        int t = __shfl_up_sync(0xffffffffu, v, o);
        if (lane >= o) v += t;
    }
    if (lane == 31) smem32[wid] = v;
    __syncthreads();
    if (wid == 0) {
        int w = (lane < 8) ? smem32[lane] : 0;
        #pragma unroll
        for (int o = 1; o < 8; o <<= 1) {
            int t = __shfl_up_sync(0xffffffffu, w, o);
            if (lane >= o) w += t;
        }
        if (lane < 8) smem32[lane] = w;
    }
    __syncthreads();
    return v + (wid > 0 ? smem32[wid - 1] : 0);
}

__global__ __launch_bounds__(256) void scan1_kernel(int M) {
    __shared__ int sm32[32];
    int i = blockIdx.x * 256 + threadIdx.x;
    int d = (i < M) ? g_DEGI[i] : 0;
    int incl = block_incl_scan(d, sm32);
    if (threadIdx.x == 255) g_PART[blockIdx.x] = incl;
}

__global__ __launch_bounds__(256) void scan2_kernel(int nb) {
    __shared__ int sm32[32];
    int tid = threadIdx.x;
    int v = (tid < nb) ? g_PART[tid] : 0;
    int incl = block_incl_scan(v, sm32);
    if (tid < nb) g_PART[tid] = incl - v;   // exclusive
}

__global__ __launch_bounds__(256) void scan3_kernel(int M) {
    __shared__ int sm32[32];
    int i = blockIdx.x * 256 + threadIdx.x;
    int d = (i < M) ? g_DEGI[i] : 0;
    int incl = block_incl_scan(d, sm32);
    int off = g_PART[blockIdx.x] + incl - d;
    if (i < M) {
        g_ROWPTR[i] = off;
        g_CUR[i]    = off;
        if (i == M - 1) g_ROWPTR[M] = off + d;
    }
}

__global__ void fill_kernel(const void* __restrict__ ei, int E) {
    int e = blockIdx.x * blockDim.x + threadIdx.x;
    if (e >= E) return;
    int is64 = g_is64;
    int s = edge_at(ei, is64, e);
    int d = edge_at(ei, is64, (long long)E + e);
    int pos = atomicAdd(&g_CUR[d], 1);
    g_SRC[pos] = s;
    g_NRM[pos] = g_DINV[s] * g_DINV[d];
}

// ---------------------------------------------------------------------------
__global__ void w1r_kernel(const float* __restrict__ W1) {
    int idx = blockIdx.x * blockDim.x + threadIdx.x;
    if (idx < CIN * CH) g_W1R[idx] = to_tf32(W1[idx]);
}

// ---------------------------------------------------------------------------
// GEMM1: H = X @ W1 via mma.sync.m16n8k8 tf32 (R12 shape), fp16 output.
// CTA 128x256, 8 warps (4m x 2n), warp tile 32x128. cp.async double buffer.
// ---------------------------------------------------------------------------
__global__ __launch_bounds__(256, 1) void gemm1_mma_kernel(
    const float* __restrict__ X, int M)
{
    extern __shared__ float sm[];
    uint32_t smb = smem_u32(sm);

    int tid  = threadIdx.x;
    int wid  = tid >> 5;
    int lane = tid & 31;
    int gid  = lane >> 2;
    int tig  = lane & 3;
    int wm   = wid >> 1;
    int wn   = wid & 1;

    int m0 = blockIdx.x * CTA_M;

    float acc[2][16][4];
    #pragma unroll
    for (int i = 0; i < 2; i++)
        #pragma unroll
        for (int j = 0; j < 16; j++)
            #pragma unroll
            for (int k = 0; k < 4; k++) acc[i][j][k] = 0.0f;

    auto issue = [&](int s, int buf) {
        uint32_t baseA = smb + buf * SM_STAGE;
        uint32_t baseB = baseA + SM_A_BYTES;
        #pragma unroll
        for (int it = 0; it < 4; it++) {
            int id  = it * 256 + tid;
            int ar = id >> 3, akq = id & 7;
            int grow = m0 + ar; if (grow > M - 1) grow = M - 1;
            cp_async16(baseA + (uint32_t)(ar * APAD + akq * 4) * 4,
                       X + (size_t)grow * CIN + s * CTA_K + akq * 4);
        }
        #pragma unroll
        for (int it = 0; it < 8; it++) {
            int id  = it * 256 + tid;
            int bk = id >> 6, bnc = id & 63;
            cp_async16(baseB + (uint32_t)(bk * BPAD + bnc * 4) * 4,
                       g_W1R + (size_t)(s * CTA_K + bk) * CH + bnc * 4);
        }
    };

    issue(0, 0);
    CP_COMMIT();

    for (int s = 0; s < NSTG; s++) {
        int buf = s & 1;
        if (s + 1 < NSTG) {
            issue(s + 1, buf ^ 1);
            CP_COMMIT();
            CP_WAIT(1);
        } else {
            CP_WAIT(0);
        }
        __syncthreads();

        const float* sA = sm + buf * (SM_STAGE / 4);
        const float* sB = sA + (SM_A_BYTES / 4);

        #pragma unroll
        for (int ks = 0; ks < 4; ks++) {
            float a[2][4];
            #pragma unroll
            for (int mt = 0; mt < 2; mt++) {
                int r = wm * 32 + mt * 16 + gid;
                int c = ks * 8 + tig;
                a[mt][0] = to_tf32(sA[r * APAD + c]);
                a[mt][1] = to_tf32(sA[(r + 8) * APAD + c]);
                a[mt][2] = to_tf32(sA[r * APAD + c + 4]);
                a[mt][3] = to_tf32(sA[(r + 8) * APAD + c + 4]);
            }
            float b[16][2];
            #pragma unroll
            for (int nt = 0; nt < 16; nt++) {
                int kk = ks * 8 + tig;
                int cc = wn * 128 + nt * 8 + gid;
                b[nt][0] = sB[kk * BPAD + cc];
                b[nt][1] = sB[(kk + 4) * BPAD + cc];
            }
            #pragma unroll
            for (int mt = 0; mt < 2; mt++)
                #pragma unroll
                for (int nt = 0; nt < 16; nt++)
                    mma_tf32(acc[mt][nt], a[mt], b[nt]);
        }
        __syncthreads();
    }

    #pragma unroll
    for (int mt = 0; mt < 2; mt++) {
        int r0 = m0 + wm * 32 + mt * 16 + gid;
        #pragma unroll
        for (int nt = 0; nt < 16; nt++) {
            int c = wn * 128 + nt * 8 + 2 * tig;
            if (r0 < M)
                *(__half2*)(g_H + (size_t)r0 * CH + c) =
                    __floats2half2_rn(acc[mt][nt][0], acc[mt][nt][1]);
            if (r0 + 8 < M)
                *(__half2*)(g_H + (size_t)(r0 + 8) * CH + c) =
                    __floats2half2_rn(acc[mt][nt][2], acc[mt][nt][3]);
        }
    }
}

// ---------------------------------------------------------------------------
// threefry2x32, key = (0, 42), partitionable mode: bits = o0 ^ o1
// ---------------------------------------------------------------------------
__device__ __forceinline__ void threefry2x32(unsigned c0, unsigned c1,
                                             unsigned& o0, unsigned& o1) {
    const unsigned ks0 = 0u, ks1 = 42u;
    const unsigned ks2 = 0x1BD11BDAu ^ ks0 ^ ks1;
    unsigned x0 = c0 + ks0;
    unsigned x1 = c1 + ks1;
#define TF_ROUND(r) { x0 += x1; x1 = (x1 << (r)) | (x1 >> (32 - (r))); x1 ^= x0; }
    TF_ROUND(13) TF_ROUND(15) TF_ROUND(26) TF_ROUND(6)
    x0 += ks1; x1 += ks2 + 1u;
    TF_ROUND(17) TF_ROUND(29) TF_ROUND(16) TF_ROUND(24)
    x0 += ks2; x1 += ks0 + 2u;
    TF_ROUND(13) TF_ROUND(15) TF_ROUND(26) TF_ROUND(6)
    x0 += ks0; x1 += ks1 + 3u;
    TF_ROUND(17) TF_ROUND(29) TF_ROUND(16) TF_ROUND(24)
    x0 += ks1; x1 += ks2 + 4u;
    TF_ROUND(13) TF_ROUND(15) TF_ROUND(26) TF_ROUND(6)
    x0 += ks2; x1 += ks0 + 5u;
#undef TF_ROUND
    o0 = x0; o1 = x1;
}

__device__ __forceinline__ float dropout_elu(float acc, float bias, unsigned idx) {
    unsigned o0, o1;
    threefry2x32(0u, idx, o0, o1);
    unsigned bits = o0 ^ o1;
    float u = __uint_as_float((bits >> 9) | 0x3F800000u) - 1.0f;
    float val = acc + bias;
    val = val > 0.0f ? val : expm1f(val);
    return (u < 0.75f) ? val * (1.0f / 0.75f) : 0.0f;
}

// uint4 (8 fp16) -> 8 floats
__device__ __forceinline__ void h8_to_f(uint4 r, float* f) {
    float2 a = __half22float2(*reinterpret_cast<__half2*>(&r.x));
    float2 b = __half22float2(*reinterpret_cast<__half2*>(&r.y));
    float2 c = __half22float2(*reinterpret_cast<__half2*>(&r.z));
    float2 d = __half22float2(*reinterpret_cast<__half2*>(&r.w));
    f[0] = a.x; f[1] = a.y; f[2] = b.x; f[3] = b.y;
    f[4] = c.x; f[5] = c.y; f[6] = d.x; f[7] = d.y;
}

// ---------------------------------------------------------------------------
// Layer-1 aggregate + epilogue + fused GEMM2, fp16 rows.
// ONE warp per node: lane t holds channels [8t, 8t+8); a full 256-ch row is a
// single warp LDG.128 (512B). 4-wide edge unroll as in the proven R12 loop.
// ---------------------------------------------------------------------------
__global__ __launch_bounds__(256) void gather1_kernel(
    const float* __restrict__ b1, const float* __restrict__ W2, int M)
{
    int wrp = threadIdx.x >> 5;              // 0..7
    int t   = threadIdx.x & 31;
    int v   = blockIdx.x * 8 + wrp;
    bool active = (v < M);
    int vv = active ? v : 0;

    const uint4* __restrict__ H8 = (const uint4*)g_H;   // row = 32 uint4

    float acc[8];
    {
        float hv[8];
        h8_to_f(H8[(size_t)vv * 32 + t], hv);
        float dv = g_DINV[vv];
        float sl = dv * dv;
        #pragma unroll
        for (int k = 0; k < 8; k++) acc[k] = sl * hv[k];
    }

    int beg = active ? g_ROWPTR[vv]     : 0;
    int end = active ? g_ROWPTR[vv + 1] : 0;

    int j = beg;
    for (; j + 4 <= end; j += 4) {
        int   s0 = g_SRC[j],      s1 = g_SRC[j + 1];
        int   s2 = g_SRC[j + 2],  s3 = g_SRC[j + 3];
        float n0 = g_NRM[j],      n1 = g_NRM[j + 1];
        float n2 = g_NRM[j + 2],  n3 = g_NRM[j + 3];
        uint4 q0 = H8[(size_t)s0 * 32 + t];
        uint4 q1 = H8[(size_t)s1 * 32 + t];
        uint4 q2 = H8[(size_t)s2 * 32 + t];
        uint4 q3 = H8[(size_t)s3 * 32 + t];
        float r0[8], r1[8], r2[8], r3[8];
        h8_to_f(q0, r0); h8_to_f(q1, r1); h8_to_f(q2, r2); h8_to_f(q3, r3);
        #pragma unroll
        for (int k = 0; k < 8; k++)
            acc[k] += n0 * r0[k] + n1 * r1[k] + n2 * r2[k] + n3 * r3[k];
    }
    for (; j < end; j++) {
        int   s0 = g_SRC[j];
        float n0 = g_NRM[j];
        float r0[8];
        h8_to_f(H8[(size_t)s0 * 32 + t], r0);
        #pragma unroll
        for (int k = 0; k < 8; k++) acc[k] += n0 * r0[k];
    }

    // epilogue: bias + ELU + dropout for 8 channels, then W2 partial dot
    const float4* b14 = (const float4*)b1;
    const float4* w24 = (const float4*)W2;
    float4 bb0 = b14[2 * t], bb1 = b14[2 * t + 1];
    float4 ww0 = w24[2 * t], ww1 = w24[2 * t + 1];
    float bbf[8] = {bb0.x, bb0.y, bb0.z, bb0.w, bb1.x, bb1.y, bb1.z, bb1.w};
    float wwf[8] = {ww0.x, ww0.y, ww0.z, ww0.w, ww1.x, ww1.y, ww1.z, ww1.w};

    unsigned base = (unsigned)vv * CH + (unsigned)t * 8;
    float dot = 0.0f;
    #pragma unroll
    for (int k = 0; k < 8; k++) {
        float a = dropout_elu(acc[k], bbf[k], base + k);
        dot += a * wwf[k];
    }

    #pragma unroll
    for (int o = 16; o > 0; o >>= 1)
        dot += __shfl_xor_sync(0xffffffffu, dot, o);
    if (t == 0 && active) g_P[v] = dot;
}

// ---------------------------------------------------------------------------
// Layer-2 aggregate (CSR gather, scalar). One warp per node.
// ---------------------------------------------------------------------------
__global__ void gather2_kernel(const float* __restrict__ b2,
                               float* __restrict__ out, int M) {
    int gt   = blockIdx.x * blockDim.x + threadIdx.x;
    int warp = gt >> 5;
    int lane = gt & 31;
    if (warp >= M) return;
    int beg = g_ROWPTR[warp];
    int end = g_ROWPTR[warp + 1];
    float s = 0.0f;
    for (int e = beg + lane; e < end; e += 32)
        s += g_NRM[e] * g_P[g_SRC[e]];
    #pragma unroll
    for (int o = 16; o > 0; o >>= 1) s += __shfl_xor_sync(0xffffffffu, s, o);
    if (lane == 0) {
        float dv = g_DINV[warp];
        out[warp] = dv * dv * g_P[warp] + b2[0] + s;
    }
}

// ---------------------------------------------------------------------------
extern "C" void kernel_launch(void* const* d_in, const int* in_sizes, int n_in,
                              void* d_out, int out_size) {
    const float* x  = (const float*)d_in[0];
    const void*  ei = d_in[1];
    const float* W1 = (const float*)d_in[2];
    const float* b1 = (const float*)d_in[3];
    const float* W2 = (const float*)d_in[4];
    const float* b2 = (const float*)d_in[5];
    float* out = (float*)d_out;

    int M = in_sizes[0] / CIN;     // 50000
    int E = in_sizes[1] / 2;       // 800000
    int nb = (M + 255) / 256;      // 196

    static cudaStream_t s2 = nullptr;
    static cudaEvent_t evFork = nullptr, evJoin = nullptr;
    if (!s2) {
        cudaFuncSetAttribute(gemm1_mma_kernel,
                             cudaFuncAttributeMaxDynamicSharedMemorySize, SM_TOTAL);
        cudaStreamCreateWithFlags(&s2, cudaStreamNonBlocking);
        cudaEventCreateWithFlags(&evFork, cudaEventDisableTiming);
        cudaEventCreateWithFlags(&evJoin, cudaEventDisableTiming);
    }

    // ---- fork: CSR build on s2, GEMM1 on stream 0 ----
    cudaEventRecord(evFork, 0);
    cudaStreamWaitEvent(s2, evFork, 0);

    detect_kernel  <<<1, 32, 0, s2>>>((const unsigned*)ei, E);      // #1
    deg_zero_kernel<<<nb, 256, 0, s2>>>(M);                          // #2
    w1r_kernel<<<(CIN * CH + 255) / 256, 256>>>(W1);                 // #3 (s0)
    dim3 g1((M + CTA_M - 1) / CTA_M, 1);  // (391, 1)
    gemm1_mma_kernel<<<g1, 256, SM_TOTAL>>>(x, M);                   // #4 (s0)

    deg_acc_kernel <<<(E + 255) / 256, 256, 0, s2>>>(ei, E);         // #5
    dinv_kernel    <<<nb, 256, 0, s2>>>(M);                          // #6
    scan1_kernel   <<<nb, 256, 0, s2>>>(M);                          // #7
    scan2_kernel   <<<1, 256, 0, s2>>>(nb);                          // #8
    scan3_kernel   <<<nb, 256, 0, s2>>>(M);                          // #9
    fill_kernel    <<<(E + 255) / 256, 256, 0, s2>>>(ei, E);         // #10

    cudaEventRecord(evJoin, s2);
    cudaStreamWaitEvent(0, evJoin, 0);

    gather1_kernel<<<(M + 7) / 8, 256>>>(b1, W2, M);                 // #11
    gather2_kernel<<<(M * 32 + 255) / 256, 256>>>(b2, out, M);       // #12
}